// round 14
// baseline (speedup 1.0000x reference)
#include <cuda_runtime.h>
#include <cuda_bf16.h>
#include <cstdint>

#define Bc 2
#define Hc 16
#define Sc 2048
#define Dc 128
#define TOT (Bc*Hc*Sc*Dc)

#define BM 128
#define BN 128
#define NT 4                  // K tiles per CTA (persistent, double-buffered)
#define TILE_B (BM*Dc*2)      // 32768 B, linear (gmem-pre-swizzled) tile
#define ROWS 528              // scratch row stride: 512B payload + 16B pad (N=2 banks)
#define KSLOT (64*ROWS)       // 33792 B: K tile (32768) or f32 scratch (64 rows)

// SMEM byte offsets
#define SM_RPOS  0            // 128 floats
#define SM_CPOS  512          // 2 x 128 floats
#define SM_MBAR0 1536
#define SM_MBAR1 1544
#define SM_Q     2048         // 32768
#define SM_K0    34816        // KSLOT
#define SM_K1    (SM_K0 + KSLOT)
#define SM_TOTAL (SM_K1 + KSLOT)   // 102400

// Scratch (allocation-free rule: __device__ globals)
__device__ __nv_bfloat16 g_Qb[TOT];
__device__ __nv_bfloat16 g_Kb[TOT];
__device__ float g_pos[Bc*Sc];

// ---------------------------------------------------------------------------
// Prepass: q *= head_scale/sqrt(D) -> bf16 ; k -> bf16 ; gather positions.
// Rows are stored PRE-SWIZZLED: 16B chunk c of row r lands at chunk c^(r&7),
// so a linear bulk-copied smem tile is ldmatrix-conflict-free.
// ---------------------------------------------------------------------------
__global__ void prep_kernel(const float* __restrict__ q, const float* __restrict__ k,
                            const float* __restrict__ head_scales,
                            const float* __restrict__ positions,
                            const int* __restrict__ tok) {
    int tid = blockIdx.x * blockDim.x + threadIdx.x;
    int base = tid * 8;                       // one 16B chunk (8 bf16)
    if (base < TOT) {
        int h = (base >> 18) & (Hc - 1);      // S*D = 2^18 elems per (b,h)
        float sc = head_scales[h] * 0.08838834764831845f; // 1/sqrt(128)

        int r = base >> 7;                    // global row (128 elems/row)
        int c = (base >> 3) & 15;             // chunk within row
        int dst = (r << 7) + ((c ^ (r & 7)) << 3);

        float4 q0 = ((const float4*)q)[tid * 2];
        float4 q1 = ((const float4*)q)[tid * 2 + 1];
        __nv_bfloat162 qp[4];
        qp[0] = __floats2bfloat162_rn(q0.x * sc, q0.y * sc);
        qp[1] = __floats2bfloat162_rn(q0.z * sc, q0.w * sc);
        qp[2] = __floats2bfloat162_rn(q1.x * sc, q1.y * sc);
        qp[3] = __floats2bfloat162_rn(q1.z * sc, q1.w * sc);
        *(uint4*)(g_Qb + dst) = *(uint4*)qp;

        float4 k0 = ((const float4*)k)[tid * 2];
        float4 k1 = ((const float4*)k)[tid * 2 + 1];
        __nv_bfloat162 kp[4];
        kp[0] = __floats2bfloat162_rn(k0.x, k0.y);
        kp[1] = __floats2bfloat162_rn(k0.z, k0.w);
        kp[2] = __floats2bfloat162_rn(k1.x, k1.y);
        kp[3] = __floats2bfloat162_rn(k1.z, k1.w);
        *(uint4*)(g_Kb + dst) = *(uint4*)kp;
    }
    if (tid < Bc * Sc) {
        g_pos[tid] = positions[tok[tid]];
    }
}

// ---------------------------------------------------------------------------
// Helpers
// ---------------------------------------------------------------------------
__device__ __forceinline__ void ldsm_x4(uint32_t addr, uint32_t* r) {
    asm volatile("ldmatrix.sync.aligned.m8n8.x4.shared.b16 {%0,%1,%2,%3}, [%4];\n"
                 : "=r"(r[0]), "=r"(r[1]), "=r"(r[2]), "=r"(r[3]) : "r"(addr));
}
__device__ __forceinline__ void mma_16816(float* c, const uint32_t* a, uint32_t b0, uint32_t b1) {
    asm volatile("mma.sync.aligned.m16n8k16.row.col.f32.bf16.bf16.f32 "
                 "{%0,%1,%2,%3}, {%4,%5,%6,%7}, {%8,%9}, {%0,%1,%2,%3};\n"
                 : "+f"(c[0]), "+f"(c[1]), "+f"(c[2]), "+f"(c[3])
                 : "r"(a[0]), "r"(a[1]), "r"(a[2]), "r"(a[3]), "r"(b0), "r"(b1));
}
__device__ __forceinline__ void mbar_init(uint32_t mbar, uint32_t cnt) {
    asm volatile("mbarrier.init.shared.b64 [%0], %1;" :: "r"(mbar), "r"(cnt) : "memory");
}
__device__ __forceinline__ void mbar_expect(uint32_t mbar, uint32_t bytes) {
    asm volatile("mbarrier.arrive.expect_tx.shared.b64 _, [%0], %1;"
                 :: "r"(mbar), "r"(bytes) : "memory");
}
__device__ __forceinline__ void bulk_g2s(uint32_t dst, const void* src, uint32_t bytes, uint32_t mbar) {
    asm volatile("cp.async.bulk.shared::cta.global.mbarrier::complete_tx::bytes "
                 "[%0], [%1], %2, [%3];"
                 :: "r"(dst), "l"(src), "r"(bytes), "r"(mbar) : "memory");
}
__device__ __forceinline__ void bulk_s2g(void* dst, uint32_t src, uint32_t bytes) {
    asm volatile("cp.async.bulk.global.shared::cta.bulk_group [%0], [%1], %2;"
                 :: "l"(dst), "r"(src), "r"(bytes) : "memory");
}
__device__ __forceinline__ void mbar_wait(uint32_t mbar, uint32_t parity) {
    uint32_t done;
    asm volatile(
        "{\n\t.reg .pred p;\n\t"
        "mbarrier.try_wait.parity.acquire.cta.shared::cta.b64 p, [%1], %2;\n\t"
        "selp.b32 %0, 1, 0, p;\n\t}"
        : "=r"(done) : "r"(mbar), "r"(parity) : "memory");
    if (!done) {
        asm volatile(
            "{\n\t.reg .pred P1;\n\t"
            "WL_%=:\n\t"
            "mbarrier.try_wait.parity.acquire.cta.shared::cta.b64 P1, [%0], %1, 0x989680;\n\t"
            "@P1 bra.uni WD_%=;\n\t"
            "bra.uni WL_%=;\n\t"
            "WD_%=:\n\t}"
            :: "r"(mbar), "r"(parity) : "memory");
    }
}

// ---------------------------------------------------------------------------
// Score kernel: per CTA fixed (z, mT); sweeps NT=4 K-tiles of 128 cols.
// TMA bulk staging G2S; gmem-pre-swizzled tiles; reg-double-buffered frags.
// Epilogue: bias fused at STS into padded-stride linear scratch (dead cur K
// buffer), then per-row cp.async.bulk S2G (TMA store: zero L1 wavefronts).
// 8 warps, warp tile 32x64, 2 CTAs/SM.
// ---------------------------------------------------------------------------
__global__ void __launch_bounds__(256, 2)
score_kernel(float* __restrict__ out, const float* __restrict__ slopes) {
    extern __shared__ char smem_raw[];
    const uint32_t sb = (uint32_t)__cvta_generic_to_shared(smem_raw);
    float* rowPos  = (float*)(smem_raw + SM_RPOS);
    float* colPosB = (float*)(smem_raw + SM_CPOS);

    const int nT0 = blockIdx.x * NT;
    const int mT  = blockIdx.y;
    const int z   = blockIdx.z;           // b*H + h
    const int b   = z >> 4;
    const int h   = z & 15;
    const int t   = threadIdx.x;

    const float slope = __ldg(slopes + h);
    const size_t zoff = (size_t)z * Sc * Dc;

    if (t == 0) {
        mbar_init(sb + SM_MBAR0, 1);
        mbar_init(sb + SM_MBAR1, 1);
    }
    __syncthreads();

    if (t == 0) {
        mbar_expect(sb + SM_MBAR0, 2 * TILE_B);
        bulk_g2s(sb + SM_Q,  g_Qb + zoff + (size_t)mT * BM * Dc, TILE_B, sb + SM_MBAR0);
        bulk_g2s(sb + SM_K0, g_Kb + zoff + (size_t)nT0 * BN * Dc, TILE_B, sb + SM_MBAR0);
    }

    if (t < BM)       rowPos[t]       = g_pos[b * Sc + mT * BM + t] * slope;
    else              colPosB[t - BM] = g_pos[b * Sc + nT0 * BN + (t - BM)] * slope; // buf 0
    __syncthreads();

    const int lane = t & 31, wid = t >> 5;
    const int wm = (wid & 3) * 32;   // warp m offset
    const int wn = (wid >> 2) * 64;  // warp n offset
    const int lr = lane & 15;
    const int hsel = lane >> 4;      // chunk half-select (0/1)
    const int x  = lr & 7;           // swizzle key (row & 7)
    const int qr0 = lane >> 2;       // 0..7
    const int cc0 = (lane & 3) * 2;

    // Row base addresses (256B row stride, linear tiles)
    uint32_t aBase[2];
    #pragma unroll
    for (int im = 0; im < 2; im++)
        aBase[im] = sb + SM_Q + (uint32_t)((wm + im * 16 + lr) << 8);
    uint32_t bRow[4];
    #pragma unroll
    for (int in2 = 0; in2 < 4; in2++)
        bRow[in2] = (uint32_t)((wn + in2 * 16 + lr) << 8);

    const size_t outBase = (size_t)z * Sc * Sc;
    const int myPass = wm >> 6;          // 0: rows 0-63, 1: rows 64-127
    const int lrB = wm & 63;             // 0 or 32

    for (int it = 0; it < NT; it++) {
        const int cur = it & 1, nxt = cur ^ 1;
        const uint32_t kb = sb + SM_K0 + (uint32_t)cur * KSLOT;

        // Prefetch next K tile (TMA) + next colPos into the other buffer
        if (it < NT - 1) {
            if (t == 0) {
                const uint32_t mb = sb + (nxt ? SM_MBAR1 : SM_MBAR0);
                mbar_expect(mb, TILE_B);
                bulk_g2s(sb + SM_K0 + (uint32_t)nxt * KSLOT,
                         g_Kb + zoff + (size_t)(nT0 + it + 1) * BN * Dc, TILE_B, mb);
            }
            if (t < BN)
                colPosB[nxt * BN + t] = g_pos[b * Sc + (nT0 + it + 1) * BN + t] * slope;
        }

        // Wait for current tile(s): mbar[it&1], parity (it>>1)&1
        mbar_wait(sb + (cur ? SM_MBAR1 : SM_MBAR0), (it >> 1) & 1);

        // ---- compute 128x128 tile, register-double-buffered fragments ----
        float acc[2][8][4];
        #pragma unroll
        for (int im = 0; im < 2; im++)
            #pragma unroll
            for (int in = 0; in < 8; in++)
                #pragma unroll
                for (int r = 0; r < 4; r++) acc[im][in][r] = 0.0f;

        uint32_t a[2][2][4];   // [buf][im][reg]
        uint32_t brf[2][4][4]; // [buf][in2][reg]

        // k-step chunk offset with swizzle: ((2*kk + hsel) ^ x) * 16
        #pragma unroll
        for (int im = 0; im < 2; im++)
            ldsm_x4(aBase[im] + (uint32_t)((hsel ^ x) << 4), a[0][im]);
        #pragma unroll
        for (int in2 = 0; in2 < 4; in2++)
            ldsm_x4(kb + bRow[in2] + (uint32_t)((hsel ^ x) << 4), brf[0][in2]);

        #pragma unroll
        for (int kk = 0; kk < 8; kk++) {
            const int fc = kk & 1, fn = fc ^ 1;
            if (kk < 7) {
                const uint32_t ko = (uint32_t)(((2 * (kk + 1) + hsel) ^ x) << 4);
                #pragma unroll
                for (int im = 0; im < 2; im++) ldsm_x4(aBase[im] + ko, a[fn][im]);
                #pragma unroll
                for (int in2 = 0; in2 < 4; in2++) ldsm_x4(kb + bRow[in2] + ko, brf[fn][in2]);
            }
            #pragma unroll
            for (int im = 0; im < 2; im++)
                #pragma unroll
                for (int in = 0; in < 8; in++) {
                    int in2 = in >> 1, sub = in & 1;
                    mma_16816(acc[im][in], a[fc][im], brf[fc][in2][sub], brf[fc][in2][sub + 2]);
                }
        }

        __syncthreads();   // S1: all warps done reading cur K tile -> scratch

        // ---- epilogue: bias at STS into padded linear scratch, TMA S2G ----
        // scratch: 64 rows; row r at byte ROWS*r (512B payload + 16B pad)
        char* scrP = smem_raw + SM_K0 + cur * KSLOT;
        const uint32_t scrA = sb + SM_K0 + (uint32_t)cur * KSLOT;
        const float* cp = colPosB + cur * BN;

        #pragma unroll
        for (int p = 0; p < 2; p++) {
            if (myPass == p) {
                // row lr0 = lrB + im*16 + 8*half + qr0 ; byte = ROWS*lr0 + 4*col
                char* laneScr = scrP + ROWS * (lrB + qr0) + 4 * wn + 8 * (lane & 3);
                #pragma unroll
                for (int im = 0; im < 2; im++) {
                    const int gr = wm + im * 16 + qr0;
                    const float prA = rowPos[gr];
                    const float prB = rowPos[gr + 8];
                    char* baseA = laneScr + ROWS * (im * 16);
                    char* baseB = baseA + ROWS * 8;
                    #pragma unroll
                    for (int in = 0; in < 8; in++) {
                        const int cl = wn + in * 8 + cc0;
                        const float pc0 = cp[cl];
                        const float pc1 = cp[cl + 1];
                        float2 vA, vB;
                        vA.x = acc[im][in][0] - prA + pc0;
                        vA.y = acc[im][in][1] - prA + pc1;
                        vB.x = acc[im][in][2] - prB + pc0;
                        vB.y = acc[im][in][3] - prB + pc1;
                        *(float2*)(baseA + 32 * in) = vA;
                        *(float2*)(baseB + 32 * in) = vB;
                    }
                }
            }
            __syncthreads();   // scratch fully written
            if (t < 64) {
                const uint32_t src = scrA + (uint32_t)(ROWS * t);
                float* dst = out + outBase + (size_t)(mT * BM + p * 64 + t) * Sc
                                 + (size_t)(nT0 + it) * BN;
                bulk_s2g(dst, src, 512u);
                asm volatile("cp.async.bulk.commit_group;" ::: "memory");
                asm volatile("cp.async.bulk.wait_group.read 0;" ::: "memory");
            }
            __syncthreads();   // scratch reads done -> reusable
        }
    }
}

// ---------------------------------------------------------------------------
extern "C" void kernel_launch(void* const* d_in, const int* in_sizes, int n_in,
                              void* d_out, int out_size) {
    const float* q         = (const float*)d_in[0];
    const float* k         = (const float*)d_in[1];
    const float* hs        = (const float*)d_in[2];
    const float* slopes    = (const float*)d_in[3];
    const float* positions = (const float*)d_in[4];
    const int*   tok       = (const int*)d_in[5];
    float* out = (float*)d_out;

    prep_kernel<<<TOT / 8 / 256, 256>>>(q, k, hs, positions, tok);

    cudaFuncSetAttribute(score_kernel, cudaFuncAttributeMaxDynamicSharedMemorySize, SM_TOTAL);
    dim3 grid(Sc / BN / NT, Sc / BM, Bc * Hc);
    score_kernel<<<grid, 256, SM_TOTAL>>>(out, slopes);
}

// round 15
// speedup vs baseline: 1.2296x; 1.2296x over previous
#include <cuda_runtime.h>
#include <cuda_bf16.h>
#include <cstdint>

#define Bc 2
#define Hc 16
#define Sc 2048
#define Dc 128
#define TOT (Bc*Hc*Sc*Dc)

#define BM 128
#define BN 128
#define NT 4                  // K tiles per CTA (persistent, double-buffered)
#define TILE_B (BM*Dc)        // 16384 B, fp8 linear (gmem-pre-swizzled) tile

// SMEM byte offsets
#define SM_RPOS  0            // 128 floats
#define SM_CPOS  512          // 2 x 128 floats
#define SM_MBAR0 1536
#define SM_MBAR1 1544
#define SM_Q     2048         // 16384
#define SM_K0    18432        // 2 x 16384
#define SM_TOTAL 51200

// Scratch (allocation-free rule: __device__ globals)
__device__ uint8_t g_Qb[TOT];   // e4m3
__device__ uint8_t g_Kb[TOT];   // e4m3
__device__ float g_pos[Bc*Sc];

// ---------------------------------------------------------------------------
// Prepass: q *= head_scale/sqrt(D) -> e4m3 ; k -> e4m3 ; gather positions.
// Rows (128 fp8 = 128B = 8 x 16B chunks) stored PRE-SWIZZLED: chunk c of row
// r lands at chunk c^(r&7), so linear bulk-copied tiles are ldsm-conflict-free.
// ---------------------------------------------------------------------------
__device__ __forceinline__ uint16_t f2_e4m3(float lo, float hi) {
    uint16_t v;
    asm("cvt.rn.satfinite.e4m3x2.f32 %0, %1, %2;" : "=h"(v) : "f"(hi), "f"(lo));
    return v;
}

__global__ void prep_kernel(const float* __restrict__ q, const float* __restrict__ k,
                            const float* __restrict__ head_scales,
                            const float* __restrict__ positions,
                            const int* __restrict__ tok) {
    int tid = blockIdx.x * blockDim.x + threadIdx.x;
    int base = tid * 16;                      // one 16B fp8 chunk (16 elems)
    if (base < TOT) {
        int h = (base >> 18) & (Hc - 1);      // S*D = 2^18 elems per (b,h)
        float sc = head_scales[h] * 0.08838834764831845f; // 1/sqrt(128)

        int r = base >> 7;                    // global row (128 elems/row)
        int c = (base >> 4) & 7;              // 16B chunk within row
        int dst = (r << 7) + ((c ^ (r & 7)) << 4);

        uint16_t qh[8], kh[8];
        #pragma unroll
        for (int j = 0; j < 4; j++) {
            float4 qv = ((const float4*)q)[tid * 4 + j];
            qh[2*j]   = f2_e4m3(qv.x * sc, qv.y * sc);
            qh[2*j+1] = f2_e4m3(qv.z * sc, qv.w * sc);
            float4 kv = ((const float4*)k)[tid * 4 + j];
            kh[2*j]   = f2_e4m3(kv.x, kv.y);
            kh[2*j+1] = f2_e4m3(kv.z, kv.w);
        }
        *(uint4*)(g_Qb + dst) = *(uint4*)qh;
        *(uint4*)(g_Kb + dst) = *(uint4*)kh;
    }
    if (tid < Bc * Sc) {
        g_pos[tid] = positions[tok[tid]];
    }
}

// ---------------------------------------------------------------------------
// Helpers
// ---------------------------------------------------------------------------
__device__ __forceinline__ void ldsm_x4(uint32_t addr, uint32_t* r) {
    asm volatile("ldmatrix.sync.aligned.m8n8.x4.shared.b16 {%0,%1,%2,%3}, [%4];\n"
                 : "=r"(r[0]), "=r"(r[1]), "=r"(r[2]), "=r"(r[3]) : "r"(addr));
}
__device__ __forceinline__ void mma_fp8(float* c, const uint32_t* a, uint32_t b0, uint32_t b1) {
    asm volatile("mma.sync.aligned.m16n8k32.row.col.f32.e4m3.e4m3.f32 "
                 "{%0,%1,%2,%3}, {%4,%5,%6,%7}, {%8,%9}, {%0,%1,%2,%3};\n"
                 : "+f"(c[0]), "+f"(c[1]), "+f"(c[2]), "+f"(c[3])
                 : "r"(a[0]), "r"(a[1]), "r"(a[2]), "r"(a[3]), "r"(b0), "r"(b1));
}
__device__ __forceinline__ void mbar_init(uint32_t mbar, uint32_t cnt) {
    asm volatile("mbarrier.init.shared.b64 [%0], %1;" :: "r"(mbar), "r"(cnt) : "memory");
}
__device__ __forceinline__ void mbar_expect(uint32_t mbar, uint32_t bytes) {
    asm volatile("mbarrier.arrive.expect_tx.shared.b64 _, [%0], %1;"
                 :: "r"(mbar), "r"(bytes) : "memory");
}
__device__ __forceinline__ void bulk_g2s(uint32_t dst, const void* src, uint32_t bytes, uint32_t mbar) {
    asm volatile("cp.async.bulk.shared::cta.global.mbarrier::complete_tx::bytes "
                 "[%0], [%1], %2, [%3];"
                 :: "r"(dst), "l"(src), "r"(bytes), "r"(mbar) : "memory");
}
__device__ __forceinline__ void mbar_wait(uint32_t mbar, uint32_t parity) {
    uint32_t done;
    asm volatile(
        "{\n\t.reg .pred p;\n\t"
        "mbarrier.try_wait.parity.acquire.cta.shared::cta.b64 p, [%1], %2;\n\t"
        "selp.b32 %0, 1, 0, p;\n\t}"
        : "=r"(done) : "r"(mbar), "r"(parity) : "memory");
    if (!done) {
        asm volatile(
            "{\n\t.reg .pred P1;\n\t"
            "WL_%=:\n\t"
            "mbarrier.try_wait.parity.acquire.cta.shared::cta.b64 P1, [%0], %1, 0x989680;\n\t"
            "@P1 bra.uni WD_%=;\n\t"
            "bra.uni WL_%=;\n\t"
            "WD_%=:\n\t}"
            :: "r"(mbar), "r"(parity) : "memory");
    }
}

// ---------------------------------------------------------------------------
// Score kernel: per CTA fixed (z, mT); sweeps NT=4 K-tiles of 128 cols.
// fp8 e4m3 MMA (m16n8k32, 4 k-steps); TMA bulk staging; gmem-pre-swizzled
// tiles; reg-double-buffered fragments; direct-STG epilogue (proven best).
// 8 warps, warp tile 32x64, 2 CTAs/SM.
// ---------------------------------------------------------------------------
__global__ void __launch_bounds__(256, 2)
score_kernel(float* __restrict__ out, const float* __restrict__ slopes) {
    extern __shared__ char smem_raw[];
    const uint32_t sb = (uint32_t)__cvta_generic_to_shared(smem_raw);
    float* rowPos  = (float*)(smem_raw + SM_RPOS);
    float* colPosB = (float*)(smem_raw + SM_CPOS);

    const int nT0 = blockIdx.x * NT;
    const int mT  = blockIdx.y;
    const int z   = blockIdx.z;           // b*H + h
    const int b   = z >> 4;
    const int h   = z & 15;
    const int t   = threadIdx.x;

    const float slope = __ldg(slopes + h);
    const size_t zoff = (size_t)z * Sc * Dc;

    if (t == 0) {
        mbar_init(sb + SM_MBAR0, 1);
        mbar_init(sb + SM_MBAR1, 1);
    }
    __syncthreads();

    if (t == 0) {
        mbar_expect(sb + SM_MBAR0, 2 * TILE_B);
        bulk_g2s(sb + SM_Q,  g_Qb + zoff + (size_t)mT * BM * Dc, TILE_B, sb + SM_MBAR0);
        bulk_g2s(sb + SM_K0, g_Kb + zoff + (size_t)nT0 * BN * Dc, TILE_B, sb + SM_MBAR0);
    }

    if (t < BM)       rowPos[t]       = g_pos[b * Sc + mT * BM + t] * slope;
    else              colPosB[t - BM] = g_pos[b * Sc + nT0 * BN + (t - BM)] * slope; // buf 0
    __syncthreads();

    const int lane = t & 31, wid = t >> 5;
    const int wm = (wid & 3) * 32;   // warp m offset
    const int wn = (wid >> 2) * 64;  // warp n offset
    const int lr = lane & 15;
    const int hsel = lane >> 4;      // chunk half-select (0/1)
    const int x  = lr & 7;           // swizzle key (row & 7)
    const int qr0 = lane >> 2;       // 0..7
    const int cc0 = (lane & 3) * 2;

    // Row base addresses (128B row stride, linear fp8 tiles)
    uint32_t aBase[2];
    #pragma unroll
    for (int im = 0; im < 2; im++)
        aBase[im] = sb + SM_Q + (uint32_t)((wm + im * 16 + lr) << 7);
    uint32_t bRow[4];
    #pragma unroll
    for (int in2 = 0; in2 < 4; in2++)
        bRow[in2] = (uint32_t)((wn + in2 * 16 + lr) << 7);

    const size_t outBase = (size_t)z * Sc * Sc;

    for (int it = 0; it < NT; it++) {
        const int cur = it & 1, nxt = cur ^ 1;
        const uint32_t kb = sb + SM_K0 + (uint32_t)cur * TILE_B;

        // Prefetch next K tile (TMA) + next colPos into the other buffer
        if (it < NT - 1) {
            if (t == 0) {
                const uint32_t mb = sb + (nxt ? SM_MBAR1 : SM_MBAR0);
                mbar_expect(mb, TILE_B);
                bulk_g2s(sb + SM_K0 + (uint32_t)nxt * TILE_B,
                         g_Kb + zoff + (size_t)(nT0 + it + 1) * BN * Dc, TILE_B, mb);
            }
            if (t < BN)
                colPosB[nxt * BN + t] = g_pos[b * Sc + (nT0 + it + 1) * BN + t] * slope;
        }

        // Wait for current tile(s): mbar[it&1], parity (it>>1)&1
        mbar_wait(sb + (cur ? SM_MBAR1 : SM_MBAR0), (it >> 1) & 1);

        // ---- compute 128x128 tile: 4 k-steps of k32 fp8 MMA ----
        float acc[2][8][4];
        #pragma unroll
        for (int im = 0; im < 2; im++)
            #pragma unroll
            for (int in = 0; in < 8; in++)
                #pragma unroll
                for (int r = 0; r < 4; r++) acc[im][in][r] = 0.0f;

        uint32_t a[2][2][4];   // [buf][im][reg]
        uint32_t brf[2][4][4]; // [buf][in2][reg]

        // k-step chunk offset with swizzle: ((2*kk + hsel) ^ x) * 16
        #pragma unroll
        for (int im = 0; im < 2; im++)
            ldsm_x4(aBase[im] + (uint32_t)((hsel ^ x) << 4), a[0][im]);
        #pragma unroll
        for (int in2 = 0; in2 < 4; in2++)
            ldsm_x4(kb + bRow[in2] + (uint32_t)((hsel ^ x) << 4), brf[0][in2]);

        #pragma unroll
        for (int kk = 0; kk < 4; kk++) {
            const int fc = kk & 1, fn = fc ^ 1;
            if (kk < 3) {
                const uint32_t ko = (uint32_t)(((2 * (kk + 1) + hsel) ^ x) << 4);
                #pragma unroll
                for (int im = 0; im < 2; im++) ldsm_x4(aBase[im] + ko, a[fn][im]);
                #pragma unroll
                for (int in2 = 0; in2 < 4; in2++) ldsm_x4(kb + bRow[in2] + ko, brf[fn][in2]);
            }
            #pragma unroll
            for (int im = 0; im < 2; im++)
                #pragma unroll
                for (int in = 0; in < 8; in++) {
                    int in2 = in >> 1, sub = in & 1;
                    mma_fp8(acc[im][in], a[fc][im], brf[fc][in2][sub], brf[fc][in2][sub + 2]);
                }
        }

        // ---- epilogue: out = score - slope*pos_q + slope*pos_k ----
        const float* cp = colPosB + cur * BN;
        #pragma unroll
        for (int im = 0; im < 2; im++) {
            const int rA = wm + im * 16 + qr0;
            const float prA = rowPos[rA];
            const float prB = rowPos[rA + 8];
            const size_t gRowA = (size_t)(mT * BM + rA);
            float* oA = out + outBase + gRowA * Sc + (size_t)(nT0 + it) * BN;
            float* oB = oA + 8 * Sc;
            #pragma unroll
            for (int in = 0; in < 8; in++) {
                const int cl = wn + in * 8 + cc0;
                const float pc0 = cp[cl];
                const float pc1 = cp[cl + 1];
                float2 v0, v1;
                v0.x = acc[im][in][0] - prA + pc0;
                v0.y = acc[im][in][1] - prA + pc1;
                v1.x = acc[im][in][2] - prB + pc0;
                v1.y = acc[im][in][3] - prB + pc1;
                *(float2*)(oA + cl) = v0;
                *(float2*)(oB + cl) = v1;
            }
        }

        // Guard K-buffer reuse and colPos visibility
        if (it < NT - 1) __syncthreads();
    }
}

// ---------------------------------------------------------------------------
extern "C" void kernel_launch(void* const* d_in, const int* in_sizes, int n_in,
                              void* d_out, int out_size) {
    const float* q         = (const float*)d_in[0];
    const float* k         = (const float*)d_in[1];
    const float* hs        = (const float*)d_in[2];
    const float* slopes    = (const float*)d_in[3];
    const float* positions = (const float*)d_in[4];
    const int*   tok       = (const int*)d_in[5];
    float* out = (float*)d_out;

    prep_kernel<<<TOT / 16 / 256, 256>>>(q, k, hs, positions, tok);

    cudaFuncSetAttribute(score_kernel, cudaFuncAttributeMaxDynamicSharedMemorySize, SM_TOTAL);
    dim3 grid(Sc / BN / NT, Sc / BM, Bc * Hc);
    score_kernel<<<grid, 256, SM_TOTAL>>>(out, slopes);
}

// round 17
// speedup vs baseline: 1.2493x; 1.0160x over previous
#include <cuda_runtime.h>
#include <cuda_bf16.h>
#include <cstdint>

#define Bc 2
#define Hc 16
#define Sc 2048
#define Dc 128
#define TOT (Bc*Hc*Sc*Dc)

#define BM 128
#define BN 128
#define NT 4                  // K tiles per CTA (persistent, double-buffered)
#define TILE_B (BM*Dc)        // 16384 B, fp8 linear (gmem-pre-swizzled) tile

// SMEM byte offsets
#define SM_RPOS  0            // 128 floats
#define SM_CPOS  512          // 2 x 128 floats
#define SM_MBAR0 1536
#define SM_MBAR1 1544
#define SM_Q     2048         // 16384
#define SM_K0    18432        // 2 x 16384
#define SM_TOTAL 51200

// Scratch (allocation-free rule: __device__ globals)
__device__ uint8_t g_Qb[TOT];   // e4m3
__device__ uint8_t g_Kb[TOT];   // e4m3
__device__ float g_pos[Bc*Sc];

// ---------------------------------------------------------------------------
// Prepass: q *= head_scale/sqrt(D) -> e4m3 ; k -> e4m3 ; gather positions.
// Rows (128 fp8 = 128B = 8 x 16B chunks) stored PRE-SWIZZLED: chunk c of row
// r lands at chunk c^(r&7), so linear bulk-copied tiles are ldsm-conflict-free.
// ---------------------------------------------------------------------------
__device__ __forceinline__ uint16_t f2_e4m3(float lo, float hi) {
    uint16_t v;
    asm("cvt.rn.satfinite.e4m3x2.f32 %0, %1, %2;" : "=h"(v) : "f"(hi), "f"(lo));
    return v;
}

__global__ void prep_kernel(const float* __restrict__ q, const float* __restrict__ k,
                            const float* __restrict__ head_scales,
                            const float* __restrict__ positions,
                            const int* __restrict__ tok) {
    int tid = blockIdx.x * blockDim.x + threadIdx.x;
    int base = tid * 16;                      // one 16B fp8 chunk (16 elems)
    if (base < TOT) {
        int h = (base >> 18) & (Hc - 1);      // S*D = 2^18 elems per (b,h)
        float sc = head_scales[h] * 0.08838834764831845f; // 1/sqrt(128)

        int r = base >> 7;                    // global row (128 elems/row)
        int c = (base >> 4) & 7;              // 16B chunk within row
        int dst = (r << 7) + ((c ^ (r & 7)) << 4);

        uint16_t qh[8], kh[8];
        #pragma unroll
        for (int j = 0; j < 4; j++) {
            float4 qv = ((const float4*)q)[tid * 4 + j];
            qh[2*j]   = f2_e4m3(qv.x * sc, qv.y * sc);
            qh[2*j+1] = f2_e4m3(qv.z * sc, qv.w * sc);
            float4 kv = ((const float4*)k)[tid * 4 + j];
            kh[2*j]   = f2_e4m3(kv.x, kv.y);
            kh[2*j+1] = f2_e4m3(kv.z, kv.w);
        }
        *(uint4*)(g_Qb + dst) = *(uint4*)qh;
        *(uint4*)(g_Kb + dst) = *(uint4*)kh;
    }
    if (tid < Bc * Sc) {
        g_pos[tid] = positions[tok[tid]];
    }
}

// ---------------------------------------------------------------------------
// Helpers
// ---------------------------------------------------------------------------
__device__ __forceinline__ void ldsm_x4(uint32_t addr, uint32_t* r) {
    asm volatile("ldmatrix.sync.aligned.m8n8.x4.shared.b16 {%0,%1,%2,%3}, [%4];\n"
                 : "=r"(r[0]), "=r"(r[1]), "=r"(r[2]), "=r"(r[3]) : "r"(addr));
}
__device__ __forceinline__ void mma_fp8(float* c, const uint32_t* a, uint32_t b0, uint32_t b1) {
    asm volatile("mma.sync.aligned.m16n8k32.row.col.f32.e4m3.e4m3.f32 "
                 "{%0,%1,%2,%3}, {%4,%5,%6,%7}, {%8,%9}, {%0,%1,%2,%3};\n"
                 : "+f"(c[0]), "+f"(c[1]), "+f"(c[2]), "+f"(c[3])
                 : "r"(a[0]), "r"(a[1]), "r"(a[2]), "r"(a[3]), "r"(b0), "r"(b1));
}
__device__ __forceinline__ void mbar_init(uint32_t mbar, uint32_t cnt) {
    asm volatile("mbarrier.init.shared.b64 [%0], %1;" :: "r"(mbar), "r"(cnt) : "memory");
}
__device__ __forceinline__ void mbar_expect(uint32_t mbar, uint32_t bytes) {
    asm volatile("mbarrier.arrive.expect_tx.shared.b64 _, [%0], %1;"
                 :: "r"(mbar), "r"(bytes) : "memory");
}
__device__ __forceinline__ void bulk_g2s(uint32_t dst, const void* src, uint32_t bytes, uint32_t mbar) {
    asm volatile("cp.async.bulk.shared::cta.global.mbarrier::complete_tx::bytes "
                 "[%0], [%1], %2, [%3];"
                 :: "r"(dst), "l"(src), "r"(bytes), "r"(mbar) : "memory");
}
__device__ __forceinline__ void mbar_wait(uint32_t mbar, uint32_t parity) {
    uint32_t done;
    asm volatile(
        "{\n\t.reg .pred p;\n\t"
        "mbarrier.try_wait.parity.acquire.cta.shared::cta.b64 p, [%1], %2;\n\t"
        "selp.b32 %0, 1, 0, p;\n\t}"
        : "=r"(done) : "r"(mbar), "r"(parity) : "memory");
    if (!done) {
        asm volatile(
            "{\n\t.reg .pred P1;\n\t"
            "WL_%=:\n\t"
            "mbarrier.try_wait.parity.acquire.cta.shared::cta.b64 P1, [%0], %1, 0x989680;\n\t"
            "@P1 bra.uni WD_%=;\n\t"
            "bra.uni WL_%=;\n\t"
            "WD_%=:\n\t}"
            :: "r"(mbar), "r"(parity) : "memory");
    }
}

// ---------------------------------------------------------------------------
// Score kernel: per CTA fixed (z, mT); sweeps NT=4 K-tiles of 128 cols.
// fp8 e4m3 MMA (m16n8k32, 4 k-steps); TMA bulk staging; gmem-pre-swizzled
// tiles; reg-double-buffered fragments; direct-STG epilogue with precomputed
// incremented pointers (no per-store IMADs). 8 warps, 32x64 warp tile, 2 CTA/SM.
// ---------------------------------------------------------------------------
__global__ void __launch_bounds__(256, 2)
score_kernel(float* __restrict__ out, const float* __restrict__ slopes) {
    extern __shared__ char smem_raw[];
    const uint32_t sb = (uint32_t)__cvta_generic_to_shared(smem_raw);
    float* rowPos  = (float*)(smem_raw + SM_RPOS);
    float* colPosB = (float*)(smem_raw + SM_CPOS);

    const int nT0 = blockIdx.x * NT;
    const int mT  = blockIdx.y;
    const int z   = blockIdx.z;           // b*H + h
    const int b   = z >> 4;
    const int h   = z & 15;
    const int t   = threadIdx.x;

    const float slope = __ldg(slopes + h);
    const size_t zoff = (size_t)z * Sc * Dc;

    if (t == 0) {
        mbar_init(sb + SM_MBAR0, 1);
        mbar_init(sb + SM_MBAR1, 1);
    }
    __syncthreads();

    if (t == 0) {
        mbar_expect(sb + SM_MBAR0, 2 * TILE_B);
        bulk_g2s(sb + SM_Q,  g_Qb + zoff + (size_t)mT * BM * Dc, TILE_B, sb + SM_MBAR0);
        bulk_g2s(sb + SM_K0, g_Kb + zoff + (size_t)nT0 * BN * Dc, TILE_B, sb + SM_MBAR0);
    }

    if (t < BM)       rowPos[t]       = g_pos[b * Sc + mT * BM + t] * slope;
    else              colPosB[t - BM] = g_pos[b * Sc + nT0 * BN + (t - BM)] * slope; // buf 0
    __syncthreads();

    const int lane = t & 31, wid = t >> 5;
    const int wm = (wid & 3) * 32;   // warp m offset
    const int wn = (wid >> 2) * 64;  // warp n offset
    const int lr = lane & 15;
    const int hsel = lane >> 4;      // chunk half-select (0/1)
    const int x  = lr & 7;           // swizzle key (row & 7)
    const int qr0 = lane >> 2;       // 0..7
    const int cc0 = (lane & 3) * 2;

    // Row base addresses (128B row stride, linear fp8 tiles)
    uint32_t aBase[2];
    #pragma unroll
    for (int im = 0; im < 2; im++)
        aBase[im] = sb + SM_Q + (uint32_t)((wm + im * 16 + lr) << 7);
    uint32_t bRow[4];
    #pragma unroll
    for (int in2 = 0; in2 < 4; in2++)
        bRow[in2] = (uint32_t)((wn + in2 * 16 + lr) << 7);

    // Precomputed, per-iteration-incremented output pointers (im x {A,B}).
    // A: row wm+im*16+qr0 ; B: +8 rows. Column base: nT0*BN + wn + cc0.
    float* oP[4];
    {
        const size_t colBase = (size_t)nT0 * BN + wn + cc0;
        const size_t outBase = (size_t)z * Sc * Sc;
        #pragma unroll
        for (int im = 0; im < 2; im++) {
            const size_t row = (size_t)(mT * BM + wm + im * 16 + qr0);
            oP[im * 2]     = out + outBase + row * Sc + colBase;
            oP[im * 2 + 1] = oP[im * 2] + 8 * Sc;
        }
    }
    // Bias row values (loop-invariant per im)
    float pr[4];
    #pragma unroll
    for (int im = 0; im < 2; im++) {
        pr[im * 2]     = rowPos[wm + im * 16 + qr0];
        pr[im * 2 + 1] = rowPos[wm + im * 16 + qr0 + 8];
    }

    for (int it = 0; it < NT; it++) {
        const int cur = it & 1, nxt = cur ^ 1;
        const uint32_t kb = sb + SM_K0 + (uint32_t)cur * TILE_B;

        // Prefetch next K tile (TMA) + next colPos into the other buffer
        if (it < NT - 1) {
            if (t == 0) {
                const uint32_t mb = sb + (nxt ? SM_MBAR1 : SM_MBAR0);
                mbar_expect(mb, TILE_B);
                bulk_g2s(sb + SM_K0 + (uint32_t)nxt * TILE_B,
                         g_Kb + zoff + (size_t)(nT0 + it + 1) * BN * Dc, TILE_B, mb);
            }
            if (t < BN)
                colPosB[nxt * BN + t] = g_pos[b * Sc + (nT0 + it + 1) * BN + t] * slope;
        }

        // Wait for current tile(s): mbar[it&1], parity (it>>1)&1
        mbar_wait(sb + (cur ? SM_MBAR1 : SM_MBAR0), (it >> 1) & 1);

        // ---- compute 128x128 tile: 4 k-steps of k32 fp8 MMA ----
        float acc[2][8][4];
        #pragma unroll
        for (int im = 0; im < 2; im++)
            #pragma unroll
            for (int in = 0; in < 8; in++)
                #pragma unroll
                for (int r = 0; r < 4; r++) acc[im][in][r] = 0.0f;

        uint32_t a[2][2][4];   // [buf][im][reg]
        uint32_t brf[2][4][4]; // [buf][in2][reg]

        // k-step chunk offset with swizzle: ((2*kk + hsel) ^ x) * 16
        #pragma unroll
        for (int im = 0; im < 2; im++)
            ldsm_x4(aBase[im] + (uint32_t)((hsel ^ x) << 4), a[0][im]);
        #pragma unroll
        for (int in2 = 0; in2 < 4; in2++)
            ldsm_x4(kb + bRow[in2] + (uint32_t)((hsel ^ x) << 4), brf[0][in2]);

        #pragma unroll
        for (int kk = 0; kk < 4; kk++) {
            const int fc = kk & 1, fn = fc ^ 1;
            if (kk < 3) {
                const uint32_t ko = (uint32_t)(((2 * (kk + 1) + hsel) ^ x) << 4);
                #pragma unroll
                for (int im = 0; im < 2; im++) ldsm_x4(aBase[im] + ko, a[fn][im]);
                #pragma unroll
                for (int in2 = 0; in2 < 4; in2++) ldsm_x4(kb + bRow[in2] + ko, brf[fn][in2]);
            }
            #pragma unroll
            for (int im = 0; im < 2; im++)
                #pragma unroll
                for (int in = 0; in < 8; in++) {
                    int in2 = in >> 1, sub = in & 1;
                    mma_fp8(acc[im][in], a[fc][im], brf[fc][in2][sub], brf[fc][in2][sub + 2]);
                }
        }

        // ---- epilogue: out = score - slope*pos_q + slope*pos_k ----
        // Bias column pairs hoisted (shared across im); stores at [ptr+imm].
        {
            const float* cp = colPosB + cur * BN + wn + cc0;
            float2 pcv[8];
            #pragma unroll
            for (int in = 0; in < 8; in++)
                pcv[in] = *(const float2*)(cp + in * 8);

            #pragma unroll
            for (int im = 0; im < 2; im++) {
                const float prA = pr[im * 2];
                const float prB = pr[im * 2 + 1];
                float* oA = oP[im * 2];
                float* oB = oP[im * 2 + 1];
                #pragma unroll
                for (int in = 0; in < 8; in++) {
                    const float t0 = pcv[in].x - prA;
                    const float t1 = pcv[in].y - prA;
                    const float t2 = pcv[in].x - prB;
                    const float t3 = pcv[in].y - prB;
                    float2 v0, v1;
                    v0.x = acc[im][in][0] + t0;
                    v0.y = acc[im][in][1] + t1;
                    v1.x = acc[im][in][2] + t2;
                    v1.y = acc[im][in][3] + t3;
                    *(float2*)(oA + in * 8) = v0;
                    *(float2*)(oB + in * 8) = v1;
                }
            }
        }
        #pragma unroll
        for (int j = 0; j < 4; j++) oP[j] += BN;

        // Guard K-buffer reuse and colPos visibility
        if (it < NT - 1) __syncthreads();
    }
}

// ---------------------------------------------------------------------------
extern "C" void kernel_launch(void* const* d_in, const int* in_sizes, int n_in,
                              void* d_out, int out_size) {
    const float* q         = (const float*)d_in[0];
    const float* k         = (const float*)d_in[1];
    const float* hs        = (const float*)d_in[2];
    const float* slopes    = (const float*)d_in[3];
    const float* positions = (const float*)d_in[4];
    const int*   tok       = (const int*)d_in[5];
    float* out = (float*)d_out;

    prep_kernel<<<TOT / 16 / 256, 256>>>(q, k, hs, positions, tok);

    cudaFuncSetAttribute(score_kernel, cudaFuncAttributeMaxDynamicSharedMemorySize, SM_TOTAL);
    dim3 grid(Sc / BN / NT, Sc / BM, Bc * Hc);
    score_kernel<<<grid, 256, SM_TOTAL>>>(out, slopes);
}